// round 17
// baseline (speedup 1.0000x reference)
#include <cuda_runtime.h>
#include <cstdint>

#define B 8
#define L 8192
#define NTOK (B * L)           // 65536
#define K_TOP 3687
#define K_RAND 409
#define N_DROP_ROW 4096
#define N_DROP (NTOK / 2)      // 32768
#define SEL_THREADS 1024
// dyn smem: hist 16384 + cand 65536 = 81920
#define SMEM_BYTES (16384 + 65536)

// scratch (no allocations allowed)
__device__ float g_norms[NTOK];
__device__ int   g_dropped[N_DROP];   // SORTED ascending per row

// ---------------------------------------------------------------------------
// Kernel 1: token L2 norms + full copy x -> out (proven 37us, 7.0 TB/s
// aggregate = mixed R/W ceiling). The ONLY kernel that reads x.
// ---------------------------------------------------------------------------
__global__ void norms_copy_kernel(const float4* __restrict__ x,
                                  float4* __restrict__ out) {
    int gt    = blockIdx.x * blockDim.x + threadIdx.x;
    int token = gt >> 4;
    int sub   = gt & 15;
    size_t base = (size_t)token * 128;
    float s = 0.f;
#pragma unroll
    for (int i = 0; i < 8; i++) {
        float4 v = x[base + sub + i * 16];
        out[base + sub + i * 16] = v;
        s += v.x * v.x + v.y * v.y + v.z * v.z + v.w * v.w;
    }
#pragma unroll
    for (int o = 8; o; o >>= 1) s += __shfl_xor_sync(0xFFFFFFFFu, s, o, 16);
    if (sub == 0) g_norms[token] = sqrtf(s);
}

// ---------------------------------------------------------------------------
// threefry2x32, JAX-compatible (partitionable, bit_width=32):
// bits[i] = word0 ^ word1 of threefry2x32(key=(0,42), hi=0, lo=i)
// ---------------------------------------------------------------------------
__device__ __forceinline__ uint32_t rotl32(uint32_t x, int d) {
    return (x << d) | (x >> (32 - d));
}

__device__ __forceinline__ uint32_t threefry_xor(uint32_t k1, uint32_t k2,
                                                 uint32_t x0, uint32_t x1) {
    uint32_t ks0 = k1, ks1 = k2, ks2 = k1 ^ k2 ^ 0x1BD11BDAu;
    x0 += ks0; x1 += ks1;
#define TF_R4(a,b,c,d) \
    x0 += x1; x1 = rotl32(x1, a); x1 ^= x0; \
    x0 += x1; x1 = rotl32(x1, b); x1 ^= x0; \
    x0 += x1; x1 = rotl32(x1, c); x1 ^= x0; \
    x0 += x1; x1 = rotl32(x1, d); x1 ^= x0;
    TF_R4(13, 15, 26, 6);  x0 += ks1; x1 += ks2 + 1u;
    TF_R4(17, 29, 16, 24); x0 += ks2; x1 += ks0 + 2u;
    TF_R4(13, 15, 26, 6);  x0 += ks0; x1 += ks1 + 3u;
    TF_R4(17, 29, 16, 24); x0 += ks1; x1 += ks2 + 4u;
    TF_R4(13, 15, 26, 6);  x0 += ks2; x1 += ks0 + 5u;
#undef TF_R4
    return x0 ^ x1;
}

// order-preserving float->uint map
__device__ __forceinline__ unsigned omap(float v) {
    unsigned u = __float_as_uint(v);
    return (u & 0x80000000u) ? ~u : (u | 0x80000000u);
}

// ---------------------------------------------------------------------------
// Exact k-th-largest 64-bit key among 8192 keys (bit-exact vs jax.lax.top_k).
// CONTIGUOUS layout: element l = tid*8 + j.
// key(l) = ((u64)um[l] << 32) | (0xFFFFFFFF - l)  -> distinct keys, smaller
// index wins ties. Shift-binning (monotone), warp-shuffle suffix scan, exact
// 64-bit rank-select in the boundary bin.
// ---------------------------------------------------------------------------
__device__ unsigned long long block_select(const unsigned um[8],
                                           unsigned umin, int shift,
                                           unsigned* hist, unsigned long long* cand,
                                           int k, int tid) {
    __shared__ int s_bin, s_need, s_cnt;
    __shared__ unsigned long long s_thr;
    __shared__ unsigned s_wsum[32];
    int lane = tid & 31, wid = tid >> 5;

    if (tid == 0) s_cnt = 0;
    reinterpret_cast<uint4*>(hist)[tid] = make_uint4(0u, 0u, 0u, 0u);
    __syncthreads();

#pragma unroll
    for (int j = 0; j < 8; j++)
        atomicAdd(&hist[(um[j] - umin) >> shift], 1u);
    __syncthreads();

    uint4 c = reinterpret_cast<const uint4*>(hist)[tid];
    unsigned s3 = c.w;
    unsigned s2 = c.z + s3;
    unsigned s1 = c.y + s2;
    unsigned s0 = c.x + s1;
    unsigned tot = s0;

    unsigned inc = tot;
#pragma unroll
    for (int off = 1; off < 32; off <<= 1) {
        unsigned v = __shfl_down_sync(0xFFFFFFFFu, inc, off);
        if (lane < 32 - off) inc += v;
    }
    if (lane == 0) s_wsum[wid] = inc;
    __syncthreads();
    if (wid == 0) {
        unsigned v = s_wsum[lane];
        unsigned inc2 = v;
#pragma unroll
        for (int off = 1; off < 32; off <<= 1) {
            unsigned t = __shfl_down_sync(0xFFFFFFFFu, inc2, off);
            if (lane < 32 - off) inc2 += t;
        }
        s_wsum[lane] = inc2 - v;   // exclusive: count in warps > lane
    }
    __syncthreads();

    unsigned above = s_wsum[wid] + (inc - tot);
    {
        unsigned geq0 = above + s0, abv0 = above + s1;
        unsigned geq1 = above + s1, abv1 = above + s2;
        unsigned geq2 = above + s2, abv2 = above + s3;
        unsigned geq3 = above + s3, abv3 = above;
        unsigned uk = (unsigned)k;
        if (geq0 >= uk && abv0 < uk) { s_bin = 4 * tid + 0; s_need = k - (int)abv0; }
        if (geq1 >= uk && abv1 < uk) { s_bin = 4 * tid + 1; s_need = k - (int)abv1; }
        if (geq2 >= uk && abv2 < uk) { s_bin = 4 * tid + 2; s_need = k - (int)abv2; }
        if (geq3 >= uk && abv3 < uk) { s_bin = 4 * tid + 3; s_need = k - (int)abv3; }
    }
    __syncthreads();

    int bsel = s_bin;
#pragma unroll
    for (int j = 0; j < 8; j++) {
        if ((int)((um[j] - umin) >> shift) == bsel) {
            int p = atomicAdd(&s_cnt, 1);
            int l = tid * 8 + j;                 // contiguous layout
            cand[p] = ((unsigned long long)um[j] << 32) | (unsigned)(0xFFFFFFFFu - (unsigned)l);
        }
    }
    __syncthreads();

    int cnt  = s_cnt;                            // cand holds 8192: no overflow
    int need = s_need;
    for (int i = tid; i < cnt; i += SEL_THREADS) {
        unsigned long long ki = cand[i];
        int r = 0;
        for (int j = 0; j < cnt; j++) r += (cand[j] > ki);
        if (r == need - 1) s_thr = ki;
    }
    __syncthreads();
    return s_thr;
}

// ---------------------------------------------------------------------------
// Kernel 2: per-row selection (block = batch row), contiguous layout.
// Emits the dropped list SORTED ascending via rank-order compaction
// (warp prefix scans, no atomics) -> sequential write pattern for k3.
// ---------------------------------------------------------------------------
__global__ void select_kernel() {
    extern __shared__ unsigned char smraw[];
    unsigned*           s_hist = (unsigned*)smraw;                        // 16384 B
    unsigned long long* s_cand = (unsigned long long*)(smraw + 16384);    // 65536 B
    __shared__ unsigned s_minw[32], s_maxw[32];
    __shared__ unsigned s_umin, s_span;
    __shared__ int s_woff[32];

    int row = blockIdx.x;
    int tid = threadIdx.x;
    int lane = tid & 31, wid = tid >> 5;
    const float* norms = &g_norms[row * L];

    cudaGridDependencySynchronize();   // PDL: wait for k1's g_norms

    // ---- pass 1: keys = omap(norm), contiguous l = tid*8 + j ----
    unsigned um[8];
    unsigned lmin = 0xFFFFFFFFu, lmax = 0u;
    {
        float4 n0 = *reinterpret_cast<const float4*>(&norms[tid * 8]);
        float4 n1 = *reinterpret_cast<const float4*>(&norms[tid * 8 + 4]);
        float nv[8] = {n0.x, n0.y, n0.z, n0.w, n1.x, n1.y, n1.z, n1.w};
#pragma unroll
        for (int j = 0; j < 8; j++) {
            unsigned u = omap(nv[j]);
            um[j] = u;
            lmin = min(lmin, u);
            lmax = max(lmax, u);
        }
    }
#pragma unroll
    for (int o = 16; o; o >>= 1) {
        lmin = min(lmin, __shfl_xor_sync(0xFFFFFFFFu, lmin, o));
        lmax = max(lmax, __shfl_xor_sync(0xFFFFFFFFu, lmax, o));
    }
    if (lane == 0) { s_minw[wid] = lmin; s_maxw[wid] = lmax; }
    __syncthreads();
    if (wid == 0) {
        unsigned m = s_minw[lane], M = s_maxw[lane];
#pragma unroll
        for (int o = 16; o; o >>= 1) {
            m = min(m, __shfl_xor_sync(0xFFFFFFFFu, m, o));
            M = max(M, __shfl_xor_sync(0xFFFFFFFFu, M, o));
        }
        if (lane == 0) { s_umin = m; s_span = M - m; }
    }
    __syncthreads();
    unsigned umin = s_umin;
    int shift = 20 - __clz(s_span | 1);
    if (shift < 0) shift = 0;

    unsigned long long thr = block_select(um, umin, shift, s_hist, s_cand, K_TOP, tid);
    unsigned keptmask = 0;             // bit j = element tid*8+j kept by pass 1
#pragma unroll
    for (int j = 0; j < 8; j++) {
        int l = tid * 8 + j;
        unsigned long long key =
            ((unsigned long long)um[j] << 32) | (unsigned)(0xFFFFFFFFu - (unsigned)l);
        if (key >= thr) keptmask |= (1u << j);
    }
    __syncthreads();

    // ---- pass 2: keys = bits>>9 (strictly monotone in uniform value) ----
#pragma unroll
    for (int j = 0; j < 8; j++) {
        int l = tid * 8 + j;
        unsigned bits = threefry_xor(0u, 42u, 0u, (unsigned)(row * L + l));
        um[j] = (keptmask >> j) & 1 ? 0u : (bits >> 9);
    }
    __syncthreads();

    thr = block_select(um, 0u, 11, s_hist, s_cand, K_RAND, tid);

    // final keep decision + dropped count per thread
    unsigned dropmask = 0;
#pragma unroll
    for (int j = 0; j < 8; j++) {
        int l = tid * 8 + j;
        unsigned long long key =
            ((unsigned long long)um[j] << 32) | (unsigned)(0xFFFFFFFFu - (unsigned)l);
        int kept = ((keptmask >> j) & 1) | (key >= thr ? 1 : 0);
        if (!kept) dropmask |= (1u << j);
    }
    int c = __popc(dropmask);

    // rank-order compaction: block exclusive prefix over per-thread counts
    int inc = c;
#pragma unroll
    for (int off = 1; off < 32; off <<= 1) {
        int v = __shfl_up_sync(0xFFFFFFFFu, inc, off);
        if (lane >= off) inc += v;
    }
    if (lane == 31) s_woff[wid] = inc;
    __syncthreads();
    if (wid == 0) {
        int v = (lane < 32) ? s_woff[lane] : 0;
        int inc2 = v;
#pragma unroll
        for (int off = 1; off < 32; off <<= 1) {
            int t = __shfl_up_sync(0xFFFFFFFFu, inc2, off);
            if (lane >= off) inc2 += t;
        }
        s_woff[lane] = inc2 - v;     // exclusive warp base
    }
    __syncthreads();
    int pos = row * N_DROP_ROW + s_woff[wid] + (inc - c);
#pragma unroll
    for (int j = 0; j < 8; j++) {
        if ((dropmask >> j) & 1) {
            g_dropped[pos++] = row * L + tid * 8 + j;   // sorted ascending
        }
    }
}

// ---------------------------------------------------------------------------
// Kernel 3: zero dropped tokens from the SORTED list, REVERSED order
// (descending tokens = still-dirty L2 tail from k1 first; sequential
// descending stream -> DRAM page locality). 4 tokens per 512-thread block.
// ---------------------------------------------------------------------------
__global__ void zero_list_kernel(float4* __restrict__ out) {
    int slot = (N_DROP - 1) - (blockIdx.x * 4 + (threadIdx.x >> 7));
    int j    = threadIdx.x & 127;
    cudaGridDependencySynchronize();   // PDL: wait for k2's g_dropped
    int token = g_dropped[slot];
    out[(size_t)token * 128 + j] = make_float4(0.f, 0.f, 0.f, 0.f);
}

extern "C" void kernel_launch(void* const* d_in, const int* in_sizes, int n_in,
                              void* d_out, int out_size) {
    (void)in_sizes; (void)n_in; (void)out_size;
    const float4* x   = (const float4*)d_in[0];
    float4*       out = (float4*)d_out;

    cudaFuncSetAttribute(select_kernel,
                         cudaFuncAttributeMaxDynamicSharedMemorySize, SMEM_BYTES);

    norms_copy_kernel<<<NTOK * 16 / 256, 256>>>(x, out);

    cudaLaunchAttribute pdl[1];
    pdl[0].id = cudaLaunchAttributeProgrammaticStreamSerialization;
    pdl[0].val.programmaticStreamSerializationAllowed = 1;

    {   // k2
        cudaLaunchConfig_t cfg = {};
        cfg.gridDim = dim3(B, 1, 1);
        cfg.blockDim = dim3(SEL_THREADS, 1, 1);
        cfg.dynamicSmemBytes = SMEM_BYTES;
        cfg.stream = 0;
        cfg.attrs = pdl;
        cfg.numAttrs = 1;
        cudaLaunchKernelEx(&cfg, select_kernel);
    }
    {   // k3
        cudaLaunchConfig_t cfg = {};
        cfg.gridDim = dim3(N_DROP / 4, 1, 1);
        cfg.blockDim = dim3(512, 1, 1);
        cfg.dynamicSmemBytes = 0;
        cfg.stream = 0;
        cfg.attrs = pdl;
        cfg.numAttrs = 1;
        cudaLaunchKernelEx(&cfg, zero_list_kernel, out);
    }
}